// round 4
// baseline (speedup 1.0000x reference)
#include <cuda_runtime.h>
#include <math.h>

#define Bc 4
#define Cc 64
#define Onc 64
#define Hc 128
#define Wc 128
#define HW (Hc*Wc)

// -------- scratch (device globals: allocation-free) --------
__device__ float g_om[Bc*27*HW];      // offset-conv output (mask pre-sigmoided)
__device__ float g_wT[576*Onc];       // dcn weights transposed [j][o]
__device__ float g_pre[Bc*Onc*HW];    // pre-BN output
__device__ float g_scale[Onc];
__device__ float g_shift[Onc];

// ---------------- kernel 0: transpose dcn weights [O][576] -> [576][O]
__global__ void k_transpose(const float* __restrict__ w) {
    int i = blockIdx.x*256 + threadIdx.x;
    if (i < Onc*576) {
        int o = i / 576, j = i - o*576;
        g_wT[j*Onc + o] = w[i];
    }
}

// ---------------- kernel 1: offset conv (27ch, 3x3, pad 1) + sigmoid on mask chans
__global__ void __launch_bounds__(128) k_offconv(const float* __restrict__ x,
                                                 const float* __restrict__ ow,
                                                 const float* __restrict__ ob) {
    extern __shared__ float wsh[]; // [c*9+k][28]  (27 used + pad)
    int h = blockIdx.x, b = blockIdx.y;
    int tid = threadIdx.x;                // = w (0..127)
    for (int i = tid; i < 27*576; i += 128) {
        int oc = i / 576, r = i - oc*576;
        wsh[r*28 + oc] = ow[i];
    }
    __syncthreads();

    float acc[28];
    #pragma unroll
    for (int oc = 0; oc < 27; oc++) acc[oc] = __ldg(&ob[oc]);
    acc[27] = 0.f;

    int w = tid;
    const float* xb = x + (long)b*Cc*HW;
    for (int c = 0; c < Cc; c++) {
        const float* p = xb + c*HW;
        float v[9];
        #pragma unroll
        for (int dy = 0; dy < 3; dy++) {
            int yy = h - 1 + dy;
            bool yok = (unsigned)yy < (unsigned)Hc;
            const float* row = p + yy*Wc;
            v[dy*3+0] = (yok && w >= 1)    ? row[w-1] : 0.f;
            v[dy*3+1] =  yok               ? row[w]   : 0.f;
            v[dy*3+2] = (yok && w <= Wc-2) ? row[w+1] : 0.f;
        }
        #pragma unroll
        for (int k = 0; k < 9; k++) {
            float vk = v[k];
            const float4* wr = (const float4*)&wsh[(c*9+k)*28];
            #pragma unroll
            for (int q = 0; q < 7; q++) {
                float4 wv = wr[q];
                acc[q*4+0] += vk*wv.x; acc[q*4+1] += vk*wv.y;
                acc[q*4+2] += vk*wv.z; acc[q*4+3] += vk*wv.w;
            }
        }
    }
    float* outp = g_om + ((long)b*27*HW) + h*Wc + w;
    #pragma unroll
    for (int oc = 0; oc < 27; oc++) {
        float vv = acc[oc];
        if (oc >= 18) vv = 1.f/(1.f + expf(-vv));   // sigmoid mask channels
        outp[oc*HW] = vv;
    }
}

// ---------------- kernel 2: fused deformable sampling + [64 x 576] GEMM per 32-pixel tile
__global__ void __launch_bounds__(256,2) k_dcn(const float* __restrict__ x,
                                               const float* __restrict__ dcn_b) {
    extern __shared__ float sh[];
    float*    s   = sh;                          // 32 pixels x 576 samples, stride 580
    float*    wch = sh + 32*580;                 // weight chunk [64][96] stride 100
    unsigned* pk  = (unsigned*)(wch + 6400);     // 288 packed clamped corner coords
    float4*   wt4 = (float4*)(pk + 288);         // 288 bilinear weights (validity+mask folded)

    int wt = blockIdx.x, h = blockIdx.y, b = blockIdx.z;
    int tid = threadIdx.x;
    int w0 = wt*32;

    // ---- phase 0: per-(pixel,tap) bilinear setup ----
    for (int i = tid; i < 288; i += 256) {
        int pix = i / 9, k = i - pix*9;
        int w = w0 + pix;
        const float* omp = g_om + ((long)b*27*HW) + h*Wc + w;
        float offx = omp[k*HW];
        float offy = omp[(9+k)*HW];
        float m    = omp[(18+k)*HW];
        float py = (float)(h - 1 + k/3) + offy;
        float px = (float)(w - 1 + k%3) + offx;
        float y0f = floorf(py), x0f = floorf(px);
        float wy = py - y0f, wx = px - x0f;
        int y0 = (int)fmaxf(fminf(y0f, 1e6f), -1e6f);
        int x0 = (int)fmaxf(fminf(x0f, 1e6f), -1e6f);
        int y1 = y0 + 1, x1 = x0 + 1;
        float vy0 = (y0 >= 0 && y0 < Hc) ? 1.f : 0.f;
        float vy1 = (y1 >= 0 && y1 < Hc) ? 1.f : 0.f;
        float vx0 = (x0 >= 0 && x0 < Wc) ? 1.f : 0.f;
        float vx1 = (x1 >= 0 && x1 < Wc) ? 1.f : 0.f;
        float4 wv;
        wv.x = (1.f-wy)*(1.f-wx)*m*vy0*vx0;
        wv.y = (1.f-wy)*wx      *m*vy0*vx1;
        wv.z = wy      *(1.f-wx)*m*vy1*vx0;
        wv.w = wy      *wx      *m*vy1*vx1;
        int y0c = min(max(y0,0),Hc-1), y1c = min(max(y1,0),Hc-1);
        int x0c = min(max(x0,0),Wc-1), x1c = min(max(x1,0),Wc-1);
        pk[i]  = (unsigned)y0c | ((unsigned)y1c<<8) | ((unsigned)x0c<<16) | ((unsigned)x1c<<24);
        wt4[i] = wv;
    }
    __syncthreads();

    // ---- phase 1: bilinear gather into s[pix][c*9+k] ----
    {
        int pair = tid >> 5, pix = tid & 31;
        const float* xb = x + (long)b*Cc*HW;
        for (int idx = pair; idx < 576; idx += 8) {
            int c = idx / 9, k = idx - c*9;
            int e = pix*9 + k;
            unsigned u = pk[e];
            float4 wv = wt4[e];
            int y0 = u & 255, y1 = (u>>8)&255, x0c = (u>>16)&255, x1c = (u>>24)&255;
            const float* p = xb + c*HW;
            float v = wv.x * p[y0*Wc + x0c]
                    + wv.y * p[y0*Wc + x1c]
                    + wv.z * p[y1*Wc + x0c]
                    + wv.w * p[y1*Wc + x1c];
            s[pix*580 + idx] = v;
        }
    }
    __syncthreads();

    // ---- phase 2: out[o][pix] = sum_j wT[j][o] * s[pix][j] ----
    int o = tid & 63, pg = tid >> 6;      // 4 groups x 8 pixels
    float acc[8];
    float bias = __ldg(&dcn_b[o]);
    #pragma unroll
    for (int i = 0; i < 8; i++) acc[i] = bias;

    for (int ch = 0; ch < 6; ch++) {
        for (int t = tid; t < 96*64; t += 256) {   // stage 96-wide j chunk, coalesced
            int jj = t >> 6, oo = t & 63;
            wch[oo*100 + jj] = g_wT[(ch*96 + jj)*64 + oo];
        }
        __syncthreads();
        #pragma unroll 4
        for (int jj4 = 0; jj4 < 24; jj4++) {
            float4 w4 = *(const float4*)&wch[o*100 + jj4*4];
            int j = ch*96 + jj4*4;
            #pragma unroll
            for (int i = 0; i < 8; i++) {
                float4 s4 = *(const float4*)&s[(pg*8+i)*580 + j];  // warp-broadcast
                acc[i] += w4.x*s4.x + w4.y*s4.y + w4.z*s4.z + w4.w*s4.w;
            }
        }
        __syncthreads();
    }
    float* op = g_pre + ((long)b*Onc + o)*HW + h*Wc + w0 + pg*8;
    #pragma unroll
    for (int i = 0; i < 8; i++) op[i] = acc[i];
}

// ---------------- kernel 3: per-channel batch stats (deterministic, no atomics)
__global__ void k_bnstats(const float* __restrict__ gamma, const float* __restrict__ beta) {
    __shared__ float r1[256], r2[256];
    int o = blockIdx.x, tid = threadIdx.x;
    float sm = 0.f, sq = 0.f;
    for (int b = 0; b < Bc; b++) {
        const float* p = g_pre + ((long)b*Onc + o)*HW;
        for (int i = tid; i < HW; i += 256) {
            float v = p[i]; sm += v; sq += v*v;
        }
    }
    r1[tid] = sm; r2[tid] = sq; __syncthreads();
    for (int st = 128; st > 0; st >>= 1) {
        if (tid < st) { r1[tid] += r1[tid+st]; r2[tid] += r2[tid+st]; }
        __syncthreads();
    }
    if (tid == 0) {
        float n   = (float)(Bc*HW);
        float mu  = r1[0]/n;
        float var = r2[0]/n - mu*mu;
        float sc  = __ldg(&gamma[o]) * rsqrtf(var + 1e-5f);
        g_scale[o] = sc;
        g_shift[o] = __ldg(&beta[o]) - mu*sc;
    }
}

// ---------------- kernel 4: BN apply + ReLU
__global__ void k_bnapply(float* __restrict__ out) {
    int i = blockIdx.x*256 + threadIdx.x;  // float4 index
    int e = i*4;
    int o = (e >> 14) & 63;                // plane = 16384 elems
    float4 v = *(const float4*)(g_pre + e);
    float sc = g_scale[o], sf = g_shift[o];
    float4 r;
    r.x = fmaxf(fmaf(v.x, sc, sf), 0.f);
    r.y = fmaxf(fmaf(v.y, sc, sf), 0.f);
    r.z = fmaxf(fmaf(v.z, sc, sf), 0.f);
    r.w = fmaxf(fmaf(v.w, sc, sf), 0.f);
    *(float4*)(out + e) = r;
}

extern "C" void kernel_launch(void* const* d_in, const int* in_sizes, int n_in,
                              void* d_out, int out_size) {
    const float* x  = (const float*)d_in[0];
    const float* ow = (const float*)d_in[1];
    const float* ob = (const float*)d_in[2];
    const float* dw = (const float*)d_in[3];
    const float* db = (const float*)d_in[4];
    const float* ga = (const float*)d_in[5];
    const float* be = (const float*)d_in[6];
    float* out = (float*)d_out;

    cudaFuncSetAttribute(k_offconv, cudaFuncAttributeMaxDynamicSharedMemorySize, 576*28*4);
    cudaFuncSetAttribute(k_dcn,     cudaFuncAttributeMaxDynamicSharedMemorySize, 105600);

    k_transpose<<<144, 256>>>(dw);

    dim3 g1(Hc, Bc);
    k_offconv<<<g1, 128, 576*28*4>>>(x, ow, ob);

    dim3 g2(Wc/32, Hc, Bc);
    k_dcn<<<g2, 256, 105600>>>(x, db);

    k_bnstats<<<Onc, 256>>>(ga, be);

    k_bnapply<<<(Bc*Onc*HW)/4/256, 256>>>(out);
}

// round 6
// speedup vs baseline: 1.1167x; 1.1167x over previous
#include <cuda_runtime.h>
#include <math.h>

#define Bc 4
#define Cc 64
#define Onc 64
#define Hc 128
#define Wc 128
#define HW (Hc*Wc)

// -------- scratch (device globals: allocation-free) --------
__device__ float g_om[Bc*27*HW];      // offset-conv output (mask pre-sigmoided)
__device__ float g_wT[576*Onc];       // dcn weights transposed [j][o]
__device__ float g_pre[Bc*Onc*HW];    // pre-BN output
__device__ float g_scale[Onc];
__device__ float g_shift[Onc];
__device__ float g_psum[Onc*16];
__device__ float g_psq[Onc*16];

// ---- packed fp32x2 helpers (Blackwell FFMA2, PTX-only) ----
__device__ __forceinline__ unsigned long long pack2(float lo, float hi) {
    unsigned long long r;
    asm("mov.b64 %0, {%1,%2};" : "=l"(r) : "f"(lo), "f"(hi));
    return r;
}
__device__ __forceinline__ void fma2(unsigned long long& d,
                                     unsigned long long a, unsigned long long b) {
    asm("fma.rn.f32x2 %0, %1, %2, %0;" : "+l"(d) : "l"(a), "l"(b));
}
__device__ __forceinline__ float2 unpack2(unsigned long long v) {
    float2 f;
    asm("mov.b64 {%0,%1}, %2;" : "=f"(f.x), "=f"(f.y) : "l"(v));
    return f;
}

// ---------------- kernel 0: transpose dcn weights [O][576] -> [576][O]
__global__ void k_transpose(const float* __restrict__ w) {
    int i = blockIdx.x*256 + threadIdx.x;
    if (i < Onc*576) {
        int o = i / 576, j = i - o*576;
        g_wT[j*Onc + o] = w[i];
    }
}

// ---------------- kernel 1: offset conv (27ch, 3x3, pad 1) + sigmoid on mask chans
__global__ void __launch_bounds__(128) k_offconv(const float* __restrict__ x,
                                                 const float* __restrict__ ow,
                                                 const float* __restrict__ ob) {
    extern __shared__ float wsh[]; // [c*9+k][28]  (27 used + pad); row = 112B, 16B aligned
    int h = blockIdx.x, b = blockIdx.y;
    int tid = threadIdx.x;                // = w (0..127)
    for (int i = tid; i < 27*576; i += 128) {
        int oc = i / 576, r = i - oc*576;
        wsh[r*28 + oc] = ow[i];
    }
    __syncthreads();

    unsigned long long acc2[14];
    #pragma unroll
    for (int q = 0; q < 14; q++) {
        float b0 = (2*q   < 27) ? __ldg(&ob[2*q])   : 0.f;
        float b1 = (2*q+1 < 27) ? __ldg(&ob[2*q+1]) : 0.f;
        acc2[q] = pack2(b0, b1);
    }

    int w = tid;
    const float* xb = x + (long)b*Cc*HW;
    for (int c = 0; c < Cc; c++) {
        const float* p = xb + c*HW;
        float v[9];
        #pragma unroll
        for (int dy = 0; dy < 3; dy++) {
            int yy = h - 1 + dy;
            bool yok = (unsigned)yy < (unsigned)Hc;
            const float* row = p + yy*Wc;
            v[dy*3+0] = (yok && w >= 1)    ? row[w-1] : 0.f;
            v[dy*3+1] =  yok               ? row[w]   : 0.f;
            v[dy*3+2] = (yok && w <= Wc-2) ? row[w+1] : 0.f;
        }
        #pragma unroll
        for (int k = 0; k < 9; k++) {
            unsigned long long vk2 = pack2(v[k], v[k]);
            const ulonglong2* wr = (const ulonglong2*)&wsh[(c*9+k)*28];
            #pragma unroll
            for (int q = 0; q < 7; q++) {
                ulonglong2 wv = wr[q];
                fma2(acc2[q*2+0], vk2, wv.x);
                fma2(acc2[q*2+1], vk2, wv.y);
            }
        }
    }
    float accf[28];
    #pragma unroll
    for (int q = 0; q < 14; q++) {
        float2 u = unpack2(acc2[q]);
        accf[2*q] = u.x; accf[2*q+1] = u.y;
    }
    float* outp = g_om + ((long)b*27*HW) + h*Wc + w;
    #pragma unroll
    for (int oc = 0; oc < 27; oc++) {
        float vv = accf[oc];
        if (oc >= 18) vv = 1.f/(1.f + expf(-vv));   // sigmoid mask channels
        outp[oc*HW] = vv;
    }
}

// ---------------- kernel 2: fused deformable sampling + [64 x 576] GEMM per 32-pixel tile
__global__ void __launch_bounds__(256,2) k_dcn(const float* __restrict__ x,
                                               const float* __restrict__ dcn_b) {
    extern __shared__ float sh[];
    float*    s   = sh;                          // s_t[j][pix]: 576 x 32 (pix contiguous)
    float*    wch = sh + 576*32;                 // weight chunk [64][96] stride 100
    unsigned* pk  = (unsigned*)(wch + 6400);     // 288 packed clamped corner coords
    float4*   wt4 = (float4*)(pk + 288);         // 288 bilinear weights (validity+mask folded)

    int wt = blockIdx.x, h = blockIdx.y, b = blockIdx.z;
    int tid = threadIdx.x;
    int w0 = wt*32;

    // ---- phase 0: per-(pixel,tap) bilinear setup ----
    for (int i = tid; i < 288; i += 256) {
        int pix = i / 9, k = i - pix*9;
        int w = w0 + pix;
        const float* omp = g_om + ((long)b*27*HW) + h*Wc + w;
        float offx = omp[k*HW];
        float offy = omp[(9+k)*HW];
        float m    = omp[(18+k)*HW];
        float py = (float)(h - 1 + k/3) + offy;
        float px = (float)(w - 1 + k%3) + offx;
        float y0f = floorf(py), x0f = floorf(px);
        float wy = py - y0f, wx = px - x0f;
        int y0 = (int)fmaxf(fminf(y0f, 1e6f), -1e6f);
        int x0 = (int)fmaxf(fminf(x0f, 1e6f), -1e6f);
        int y1 = y0 + 1, x1 = x0 + 1;
        float vy0 = (y0 >= 0 && y0 < Hc) ? 1.f : 0.f;
        float vy1 = (y1 >= 0 && y1 < Hc) ? 1.f : 0.f;
        float vx0 = (x0 >= 0 && x0 < Wc) ? 1.f : 0.f;
        float vx1 = (x1 >= 0 && x1 < Wc) ? 1.f : 0.f;
        float4 wv;
        wv.x = (1.f-wy)*(1.f-wx)*m*vy0*vx0;
        wv.y = (1.f-wy)*wx      *m*vy0*vx1;
        wv.z = wy      *(1.f-wx)*m*vy1*vx0;
        wv.w = wy      *wx      *m*vy1*vx1;
        int y0c = min(max(y0,0),Hc-1), y1c = min(max(y1,0),Hc-1);
        int x0c = min(max(x0,0),Wc-1), x1c = min(max(x1,0),Wc-1);
        pk[i]  = (unsigned)y0c | ((unsigned)y1c<<8) | ((unsigned)x0c<<16) | ((unsigned)x1c<<24);
        wt4[i] = wv;
    }
    __syncthreads();

    // ---- phase 1: bilinear gather into s_t[j][pix]  (j = c*9+k) ----
    {
        int pair = tid >> 5, pix = tid & 31;
        const float* xb = x + (long)b*Cc*HW;
        for (int idx = pair; idx < 576; idx += 8) {
            int c = idx / 9, k = idx - c*9;
            int e = pix*9 + k;
            unsigned u = pk[e];
            float4 wv = wt4[e];
            int y0 = u & 255, y1 = (u>>8)&255, x0c = (u>>16)&255, x1c = (u>>24)&255;
            const float* p = xb + c*HW;
            float v = wv.x * p[y0*Wc + x0c]
                    + wv.y * p[y0*Wc + x1c]
                    + wv.z * p[y1*Wc + x0c]
                    + wv.w * p[y1*Wc + x1c];
            s[idx*32 + pix] = v;
        }
    }
    __syncthreads();

    // ---- phase 2: out[o][pix] = sum_j wT[j][o] * s_t[j][pix], packed f32x2 ----
    int o = tid & 63, pg = tid >> 6;      // 4 groups x 8 pixels (4 packed pairs)
    unsigned long long acc2[4];
    float bias = __ldg(&dcn_b[o]);
    unsigned long long bias2 = pack2(bias, bias);
    #pragma unroll
    for (int i = 0; i < 4; i++) acc2[i] = bias2;

    for (int ch = 0; ch < 6; ch++) {
        for (int t = tid; t < 96*64; t += 256) {   // stage 96-wide j chunk, coalesced
            int jj = t >> 6, oo = t & 63;
            wch[oo*100 + jj] = g_wT[(ch*96 + jj)*64 + oo];
        }
        __syncthreads();
        #pragma unroll 4
        for (int jj4 = 0; jj4 < 24; jj4++) {
            float4 w4 = *(const float4*)&wch[o*100 + jj4*4];
            int j = ch*96 + jj4*4;
            float wq[4] = {w4.x, w4.y, w4.z, w4.w};
            #pragma unroll
            for (int q = 0; q < 4; q++) {
                unsigned long long wd = pack2(wq[q], wq[q]);
                const float* srow = &s[(j+q)*32 + pg*8];
                ulonglong2 a = *(const ulonglong2*)(srow);      // pixels 0-3 (2 pairs)
                ulonglong2 bb = *(const ulonglong2*)(srow + 4); // pixels 4-7 (2 pairs)
                fma2(acc2[0], a.x,  wd);
                fma2(acc2[1], a.y,  wd);
                fma2(acc2[2], bb.x, wd);
                fma2(acc2[3], bb.y, wd);
            }
        }
        __syncthreads();
    }
    float* op = g_pre + ((long)b*Onc + o)*HW + h*Wc + w0 + pg*8;
    *(ulonglong2*)(op)     = make_ulonglong2(acc2[0], acc2[1]);
    *(ulonglong2*)(op + 4) = make_ulonglong2(acc2[2], acc2[3]);
}

// ---------------- kernel 3a: partial per-channel sums (1024 blocks, deterministic)
__global__ void k_bnstats1() {
    __shared__ float r1[256], r2[256];
    int sl = blockIdx.x;       // 0..15 slice
    int o  = blockIdx.y;       // channel
    int tid = threadIdx.x;
    int b = sl >> 2, q = sl & 3;
    const float4* p = (const float4*)(g_pre + ((long)(b*Onc + o))*HW + q*4096);
    float sm = 0.f, sq = 0.f;
    #pragma unroll
    for (int i = tid; i < 1024; i += 256) {
        float4 v = p[i];
        sm += v.x + v.y + v.z + v.w;
        sq += v.x*v.x + v.y*v.y + v.z*v.z + v.w*v.w;
    }
    r1[tid] = sm; r2[tid] = sq; __syncthreads();
    for (int st = 128; st > 0; st >>= 1) {
        if (tid < st) { r1[tid] += r1[tid+st]; r2[tid] += r2[tid+st]; }
        __syncthreads();
    }
    if (tid == 0) { g_psum[o*16 + sl] = r1[0]; g_psq[o*16 + sl] = r2[0]; }
}

// ---------------- kernel 3b: finalize scale/shift
__global__ void k_bnstats2(const float* __restrict__ gamma, const float* __restrict__ beta) {
    int o = threadIdx.x;
    float sm = 0.f, sq = 0.f;
    #pragma unroll
    for (int i = 0; i < 16; i++) { sm += g_psum[o*16+i]; sq += g_psq[o*16+i]; }
    float n   = (float)(Bc*HW);
    float mu  = sm/n;
    float var = sq/n - mu*mu;
    float sc  = __ldg(&gamma[o]) * rsqrtf(var + 1e-5f);
    g_scale[o] = sc;
    g_shift[o] = __ldg(&beta[o]) - mu*sc;
}

// ---------------- kernel 4: BN apply + ReLU
__global__ void k_bnapply(float* __restrict__ out) {
    int i = blockIdx.x*256 + threadIdx.x;  // float4 index
    int e = i*4;
    int o = (e >> 14) & 63;                // plane = 16384 elems
    float4 v = *(const float4*)(g_pre + e);
    float sc = g_scale[o], sf = g_shift[o];
    float4 r;
    r.x = fmaxf(fmaf(v.x, sc, sf), 0.f);
    r.y = fmaxf(fmaf(v.y, sc, sf), 0.f);
    r.z = fmaxf(fmaf(v.z, sc, sf), 0.f);
    r.w = fmaxf(fmaf(v.w, sc, sf), 0.f);
    *(float4*)(out + e) = r;
}

extern "C" void kernel_launch(void* const* d_in, const int* in_sizes, int n_in,
                              void* d_out, int out_size) {
    const float* x  = (const float*)d_in[0];
    const float* ow = (const float*)d_in[1];
    const float* ob = (const float*)d_in[2];
    const float* dw = (const float*)d_in[3];
    const float* db = (const float*)d_in[4];
    const float* ga = (const float*)d_in[5];
    const float* be = (const float*)d_in[6];
    float* out = (float*)d_out;

    cudaFuncSetAttribute(k_offconv, cudaFuncAttributeMaxDynamicSharedMemorySize, 576*28*4);
    cudaFuncSetAttribute(k_dcn,     cudaFuncAttributeMaxDynamicSharedMemorySize, 105600);

    k_transpose<<<144, 256>>>(dw);

    dim3 g1(Hc, Bc);
    k_offconv<<<g1, 128, 576*28*4>>>(x, ow, ob);

    dim3 g2(Wc/32, Hc, Bc);
    k_dcn<<<g2, 256, 105600>>>(x, db);

    dim3 g3(16, Onc);
    k_bnstats1<<<g3, 256>>>();
    k_bnstats2<<<1, Onc>>>(ga, be);

    k_bnapply<<<(Bc*Onc*HW)/4/256, 256>>>(out);
}

// round 7
// speedup vs baseline: 1.1895x; 1.0651x over previous
#include <cuda_runtime.h>
#include <math.h>

#define Bc 4
#define Cc 64
#define Onc 64
#define Hc 128
#define Wc 128
#define HW (Hc*Wc)

// -------- scratch (device globals: allocation-free) --------
__device__ float  g_om[Bc*27*HW];       // offset-conv output (mask pre-sigmoided)
__device__ float  g_pre[Bc*Onc*HW];     // pre-BN output
__device__ unsigned g_pk [Bc*9*HW];     // packed clamped corner coords, planes [b][k][pix]
__device__ float4 g_wt4[Bc*9*HW];       // bilinear weights (validity+mask folded), [b][k][pix]
__device__ float  g_scale[Onc];
__device__ float  g_shift[Onc];
__device__ float  g_psum[Onc*16];
__device__ float  g_psq[Onc*16];

// ---- packed fp32x2 helpers (Blackwell FFMA2, PTX-only) ----
__device__ __forceinline__ unsigned long long pack2(float lo, float hi) {
    unsigned long long r;
    asm("mov.b64 %0, {%1,%2};" : "=l"(r) : "f"(lo), "f"(hi));
    return r;
}
__device__ __forceinline__ void fma2(unsigned long long& d,
                                     unsigned long long a, unsigned long long b) {
    asm("fma.rn.f32x2 %0, %1, %2, %0;" : "+l"(d) : "l"(a), "l"(b));
}
__device__ __forceinline__ float2 unpack2(unsigned long long v) {
    float2 f;
    asm("mov.b64 {%0,%1}, %2;" : "=f"(f.x), "=f"(f.y) : "l"(v));
    return f;
}

// ---------------- kernel 0: offset conv (27ch, 3x3, pad 1) + sigmoid on mask chans
__global__ void __launch_bounds__(128) k_offconv(const float* __restrict__ x,
                                                 const float* __restrict__ ow,
                                                 const float* __restrict__ ob) {
    extern __shared__ float wsh[]; // [c*9+k][28]  (27 used + pad); row = 112B, 16B aligned
    int h = blockIdx.x, b = blockIdx.y;
    int tid = threadIdx.x;                // = w (0..127)
    for (int i = tid; i < 27*576; i += 128) {
        int oc = i / 576, r = i - oc*576;
        wsh[r*28 + oc] = ow[i];
    }
    __syncthreads();

    unsigned long long acc2[14];
    #pragma unroll
    for (int q = 0; q < 14; q++) {
        float b0 = (2*q   < 27) ? __ldg(&ob[2*q])   : 0.f;
        float b1 = (2*q+1 < 27) ? __ldg(&ob[2*q+1]) : 0.f;
        acc2[q] = pack2(b0, b1);
    }

    int w = tid;
    const float* xb = x + (long)b*Cc*HW;
    for (int c = 0; c < Cc; c++) {
        const float* p = xb + c*HW;
        float v[9];
        #pragma unroll
        for (int dy = 0; dy < 3; dy++) {
            int yy = h - 1 + dy;
            bool yok = (unsigned)yy < (unsigned)Hc;
            const float* row = p + yy*Wc;
            v[dy*3+0] = (yok && w >= 1)    ? row[w-1] : 0.f;
            v[dy*3+1] =  yok               ? row[w]   : 0.f;
            v[dy*3+2] = (yok && w <= Wc-2) ? row[w+1] : 0.f;
        }
        #pragma unroll
        for (int k = 0; k < 9; k++) {
            unsigned long long vk2 = pack2(v[k], v[k]);
            const ulonglong2* wr = (const ulonglong2*)&wsh[(c*9+k)*28];
            #pragma unroll
            for (int q = 0; q < 7; q++) {
                ulonglong2 wv = wr[q];
                fma2(acc2[q*2+0], vk2, wv.x);
                fma2(acc2[q*2+1], vk2, wv.y);
            }
        }
    }
    float accf[28];
    #pragma unroll
    for (int q = 0; q < 14; q++) {
        float2 u = unpack2(acc2[q]);
        accf[2*q] = u.x; accf[2*q+1] = u.y;
    }
    float* outp = g_om + ((long)b*27*HW) + h*Wc + w;
    #pragma unroll
    for (int oc = 0; oc < 27; oc++) {
        float vv = accf[oc];
        if (oc >= 18) vv = 1.f/(1.f + expf(-vv));   // sigmoid mask channels
        outp[oc*HW] = vv;
    }
}

// ---------------- kernel 1a/1b: per-(pixel,tap) bilinear setup, fully coalesced
// handles 2 batches per launch (b0 = 0 or 2)
__global__ void __launch_bounds__(256) k_prep(int b0) {
    int e = blockIdx.x*256 + threadIdx.x;      // over 2*9*HW
    if (e >= 2*9*HW) return;
    int b   = b0 + e/(9*HW);
    int r   = e % (9*HW);
    int k   = r / HW;
    int pix = r % HW;
    int h = pix >> 7, w = pix & 127;

    const float* omb = g_om + (long)b*27*HW;
    float offx = omb[k*HW + pix];
    float offy = omb[(9+k)*HW + pix];
    float m    = omb[(18+k)*HW + pix];

    float py = (float)(h - 1 + k/3) + offy;
    float px = (float)(w - 1 + k%3) + offx;
    float y0f = floorf(py), x0f = floorf(px);
    float wy = py - y0f, wx = px - x0f;
    int y0 = (int)fmaxf(fminf(y0f, 1e6f), -1e6f);
    int x0 = (int)fmaxf(fminf(x0f, 1e6f), -1e6f);
    int y1 = y0 + 1, x1 = x0 + 1;
    float vy0 = (y0 >= 0 && y0 < Hc) ? 1.f : 0.f;
    float vy1 = (y1 >= 0 && y1 < Hc) ? 1.f : 0.f;
    float vx0 = (x0 >= 0 && x0 < Wc) ? 1.f : 0.f;
    float vx1 = (x1 >= 0 && x1 < Wc) ? 1.f : 0.f;
    float4 wv;
    wv.x = (1.f-wy)*(1.f-wx)*m*vy0*vx0;
    wv.y = (1.f-wy)*wx      *m*vy0*vx1;
    wv.z = wy      *(1.f-wx)*m*vy1*vx0;
    wv.w = wy      *wx      *m*vy1*vx1;
    int y0c = min(max(y0,0),Hc-1), y1c = min(max(y1,0),Hc-1);
    int x0c = min(max(x0,0),Wc-1), x1c = min(max(x1,0),Wc-1);

    int plane = b*9 + k;
    g_pk [plane*HW + pix] = (unsigned)y0c | ((unsigned)y1c<<8) | ((unsigned)x0c<<16) | ((unsigned)x1c<<24);
    g_wt4[plane*HW + pix] = wv;
}

// ---------------- kernel 2: fused deformable sampling + [64 x 576] GEMM, K chunked by 96
__global__ void __launch_bounds__(256) k_dcn(const float* __restrict__ x,
                                             const float* __restrict__ dw,
                                             const float* __restrict__ dcn_b) {
    __shared__ float    s[96*32];        // s_t[j'][pix] for current chunk
    __shared__ float    wch[64*100];     // weight chunk [o][96] stride 100
    __shared__ unsigned pk_s[288];       // [pix][k]
    __shared__ float4   wt4_s[288];      // [pix][k]

    int wt = blockIdx.x, h = blockIdx.y, b = blockIdx.z;
    int tid = threadIdx.x;
    int w0 = wt*32;

    // stage per-pixel bilinear setup (coalesced plane reads)
    {
        int base = h*Wc + w0;
        for (int i = tid; i < 288; i += 256) {
            int k = i >> 5, pix = i & 31;
            int g = (b*9 + k)*HW + base + pix;
            pk_s [pix*9 + k] = g_pk[g];
            wt4_s[pix*9 + k] = g_wt4[g];
        }
    }
    __syncthreads();

    int o = tid & 63, pg = tid >> 6;      // 4 groups x 8 pixels (4 packed pairs)
    int pair = tid >> 5, pix = tid & 31;  // gather roles
    const float* xb = x + (long)b*Cc*HW;

    unsigned long long acc2[4];
    float bias = __ldg(&dcn_b[o]);
    unsigned long long bias2 = pack2(bias, bias);
    #pragma unroll
    for (int i = 0; i < 4; i++) acc2[i] = bias2;

    // staging index state (strength-reduced div)
    int sjj = tid % 96, soo = tid / 96;

    for (int ch = 0; ch < 6; ch++) {
        // ---- stage weight chunk straight from dw [o][576] (coalesced reads, conflict-free STS)
        {
            int jj = sjj, oo = soo;
            #pragma unroll
            for (int it = 0; it < 24; it++) {
                wch[oo*100 + jj] = dw[oo*576 + ch*96 + jj];
                jj += 64; oo += 2;
                if (jj >= 96) { jj -= 96; oo++; }
            }
        }
        // ---- gather 96 j's for 32 pixels ----
        {
            int j0 = ch*96 + pair;
            int c = j0 / 9;
            int k = j0 - c*9;
            const float* xp = xb + c*HW;
            #pragma unroll 4
            for (int m = 0; m < 12; m++) {
                int e = pix*9 + k;
                unsigned u = pk_s[e];
                float4 wv = wt4_s[e];
                int y0 = u & 255, y1 = (u>>8)&255, x0c = (u>>16)&255, x1c = u>>24;
                float v = wv.x * xp[y0*Wc + x0c]
                        + wv.y * xp[y0*Wc + x1c]
                        + wv.z * xp[y1*Wc + x0c]
                        + wv.w * xp[y1*Wc + x1c];
                s[(pair + m*8)*32 + pix] = v;
                // advance j by 8: k -> (k+8) mod 9; c increments unless k was 0
                if (k == 0) { k = 8; } else { k--; xp += HW; }
            }
        }
        __syncthreads();

        // ---- GEMM on chunk: acc[o][pix] += wch[o][j'] * s[j'][pix] ----
        #pragma unroll 4
        for (int jj4 = 0; jj4 < 24; jj4++) {
            float4 w4 = *(const float4*)&wch[o*100 + jj4*4];
            float wq[4] = {w4.x, w4.y, w4.z, w4.w};
            #pragma unroll
            for (int q = 0; q < 4; q++) {
                unsigned long long wd = pack2(wq[q], wq[q]);
                const float* srow = &s[(jj4*4 + q)*32 + pg*8];
                ulonglong2 a  = *(const ulonglong2*)(srow);      // pixels 0-3
                ulonglong2 bb = *(const ulonglong2*)(srow + 4);  // pixels 4-7
                fma2(acc2[0], a.x,  wd);
                fma2(acc2[1], a.y,  wd);
                fma2(acc2[2], bb.x, wd);
                fma2(acc2[3], bb.y, wd);
            }
        }
        __syncthreads();
    }
    float* op = g_pre + ((long)b*Onc + o)*HW + h*Wc + w0 + pg*8;
    *(ulonglong2*)(op)     = make_ulonglong2(acc2[0], acc2[1]);
    *(ulonglong2*)(op + 4) = make_ulonglong2(acc2[2], acc2[3]);
}

// ---------------- kernel 3a: partial per-channel sums (1024 blocks, deterministic)
__global__ void k_bnstats1() {
    __shared__ float r1[256], r2[256];
    int sl = blockIdx.x;       // 0..15 slice
    int o  = blockIdx.y;       // channel
    int tid = threadIdx.x;
    int b = sl >> 2, q = sl & 3;
    const float4* p = (const float4*)(g_pre + ((long)(b*Onc + o))*HW + q*4096);
    float sm = 0.f, sq = 0.f;
    #pragma unroll
    for (int i = tid; i < 1024; i += 256) {
        float4 v = p[i];
        sm += v.x + v.y + v.z + v.w;
        sq += v.x*v.x + v.y*v.y + v.z*v.z + v.w*v.w;
    }
    r1[tid] = sm; r2[tid] = sq; __syncthreads();
    for (int st = 128; st > 0; st >>= 1) {
        if (tid < st) { r1[tid] += r1[tid+st]; r2[tid] += r2[tid+st]; }
        __syncthreads();
    }
    if (tid == 0) { g_psum[o*16 + sl] = r1[0]; g_psq[o*16 + sl] = r2[0]; }
}

// ---------------- kernel 3b: finalize scale/shift
__global__ void k_bnstats2(const float* __restrict__ gamma, const float* __restrict__ beta) {
    int o = threadIdx.x;
    float sm = 0.f, sq = 0.f;
    #pragma unroll
    for (int i = 0; i < 16; i++) { sm += g_psum[o*16+i]; sq += g_psq[o*16+i]; }
    float n   = (float)(Bc*HW);
    float mu  = sm/n;
    float var = sq/n - mu*mu;
    float sc  = __ldg(&gamma[o]) * rsqrtf(var + 1e-5f);
    g_scale[o] = sc;
    g_shift[o] = __ldg(&beta[o]) - mu*sc;
}

// ---------------- kernel 4: BN apply + ReLU
__global__ void k_bnapply(float* __restrict__ out) {
    int i = blockIdx.x*256 + threadIdx.x;  // float4 index
    int e = i*4;
    int o = (e >> 14) & 63;                // plane = 16384 elems
    float4 v = *(const float4*)(g_pre + e);
    float sc = g_scale[o], sf = g_shift[o];
    float4 r;
    r.x = fmaxf(fmaf(v.x, sc, sf), 0.f);
    r.y = fmaxf(fmaf(v.y, sc, sf), 0.f);
    r.z = fmaxf(fmaf(v.z, sc, sf), 0.f);
    r.w = fmaxf(fmaf(v.w, sc, sf), 0.f);
    *(float4*)(out + e) = r;
}

extern "C" void kernel_launch(void* const* d_in, const int* in_sizes, int n_in,
                              void* d_out, int out_size) {
    const float* x  = (const float*)d_in[0];
    const float* ow = (const float*)d_in[1];
    const float* ob = (const float*)d_in[2];
    const float* dw = (const float*)d_in[3];
    const float* db = (const float*)d_in[4];
    const float* ga = (const float*)d_in[5];
    const float* be = (const float*)d_in[6];
    float* out = (float*)d_out;

    cudaFuncSetAttribute(k_offconv, cudaFuncAttributeMaxDynamicSharedMemorySize, 576*28*4);

    dim3 g1(Hc, Bc);
    k_offconv<<<g1, 128, 576*28*4>>>(x, ow, ob);            // launch 0

    int prepBlocks = (2*9*HW + 255)/256;
    k_prep<<<prepBlocks, 256>>>(0);                         // launch 1
    k_prep<<<prepBlocks, 256>>>(2);                         // launch 2

    dim3 g2(Wc/32, Hc, Bc);
    k_dcn<<<g2, 256>>>(x, dw, db);                          // launch 3 (ncu capture slot)

    dim3 g3(16, Onc);
    k_bnstats1<<<g3, 256>>>();                              // launch 4
    k_bnstats2<<<1, Onc>>>(ga, be);                         // launch 5

    k_bnapply<<<(Bc*Onc*HW)/4/256, 256>>>(out);             // launch 6
}

// round 9
// speedup vs baseline: 1.3394x; 1.1260x over previous
#include <cuda_runtime.h>
#include <math.h>

#define Bc 4
#define Cc 64
#define Onc 64
#define Hc 128
#define Wc 128
#define HW (Hc*Wc)

// -------- scratch (device globals: allocation-free) --------
__device__ float  g_om[Bc*27*HW];       // offset-conv output (mask pre-sigmoided)
__device__ float  g_wT[576*Onc];        // dcn weights transposed [j][o]
__device__ float  g_pre[Bc*Onc*HW];     // pre-BN output
__device__ unsigned g_pk [Bc*9*HW];     // packed clamped corner coords, planes [b][k][pix]
__device__ float4 g_wt4[Bc*9*HW];       // bilinear weights (validity+mask folded), [b][k][pix]
__device__ float  g_scale[Onc];
__device__ float  g_shift[Onc];
__device__ float  g_psum[Onc*16];
__device__ float  g_psq[Onc*16];

// ---- packed fp32x2 helpers (Blackwell FFMA2, PTX-only) ----
__device__ __forceinline__ unsigned long long pack2(float lo, float hi) {
    unsigned long long r;
    asm("mov.b64 %0, {%1,%2};" : "=l"(r) : "f"(lo), "f"(hi));
    return r;
}
__device__ __forceinline__ void fma2(unsigned long long& d,
                                     unsigned long long a, unsigned long long b) {
    asm("fma.rn.f32x2 %0, %1, %2, %0;" : "+l"(d) : "l"(a), "l"(b));
}
__device__ __forceinline__ float2 unpack2(unsigned long long v) {
    float2 f;
    asm("mov.b64 {%0,%1}, %2;" : "=f"(f.x), "=f"(f.y) : "l"(v));
    return f;
}

// ---------------- kernel 0: transpose dcn weights [O][576] -> [576][O]
__global__ void k_transpose(const float* __restrict__ w) {
    int i = blockIdx.x*256 + threadIdx.x;
    if (i < Onc*576) {
        int o = i / 576, j = i - o*576;
        g_wT[j*Onc + o] = w[i];
    }
}

// ---------------- kernel 1: offset conv (27ch, 3x3, pad 1) + sigmoid on mask chans
// each block handles 2 consecutive h rows (amortizes the 63KB weight staging)
__global__ void __launch_bounds__(128) k_offconv(const float* __restrict__ x,
                                                 const float* __restrict__ ow,
                                                 const float* __restrict__ ob) {
    extern __shared__ float wsh[]; // [c*9+k][28]  (27 used + pad); row = 112B, 16B aligned
    int b = blockIdx.y;
    int tid = threadIdx.x;                // = w (0..127)
    for (int i = tid; i < 27*576; i += 128) {
        int oc = i / 576, r = i - oc*576;
        wsh[r*28 + oc] = ow[i];
    }
    __syncthreads();

    int w = tid;
    const float* xb = x + (long)b*Cc*HW;

    for (int hh = 0; hh < 2; hh++) {
        int h = blockIdx.x*2 + hh;

        unsigned long long acc2[14];
        #pragma unroll
        for (int q = 0; q < 14; q++) {
            float b0 = (2*q   < 27) ? __ldg(&ob[2*q])   : 0.f;
            float b1 = (2*q+1 < 27) ? __ldg(&ob[2*q+1]) : 0.f;
            acc2[q] = pack2(b0, b1);
        }

        for (int c = 0; c < Cc; c++) {
            const float* p = xb + c*HW;
            float v[9];
            #pragma unroll
            for (int dy = 0; dy < 3; dy++) {
                int yy = h - 1 + dy;
                bool yok = (unsigned)yy < (unsigned)Hc;
                const float* row = p + yy*Wc;
                v[dy*3+0] = (yok && w >= 1)    ? row[w-1] : 0.f;
                v[dy*3+1] =  yok               ? row[w]   : 0.f;
                v[dy*3+2] = (yok && w <= Wc-2) ? row[w+1] : 0.f;
            }
            #pragma unroll
            for (int k = 0; k < 9; k++) {
                unsigned long long vk2 = pack2(v[k], v[k]);
                const ulonglong2* wr = (const ulonglong2*)&wsh[(c*9+k)*28];
                #pragma unroll
                for (int q = 0; q < 7; q++) {
                    ulonglong2 wv = wr[q];
                    fma2(acc2[q*2+0], vk2, wv.x);
                    fma2(acc2[q*2+1], vk2, wv.y);
                }
            }
        }
        float accf[28];
        #pragma unroll
        for (int q = 0; q < 14; q++) {
            float2 u = unpack2(acc2[q]);
            accf[2*q] = u.x; accf[2*q+1] = u.y;
        }
        float* outp = g_om + ((long)b*27*HW) + h*Wc + w;
        #pragma unroll
        for (int oc = 0; oc < 27; oc++) {
            float vv = accf[oc];
            if (oc >= 18) vv = 1.f/(1.f + expf(-vv));   // sigmoid mask channels
            outp[oc*HW] = vv;
        }
    }
}

// ---------------- kernel 2: per-(pixel,tap) bilinear setup, fully coalesced (all batches)
__global__ void __launch_bounds__(256) k_prep() {
    int e = blockIdx.x*256 + threadIdx.x;      // over 4*9*HW
    if (e >= Bc*9*HW) return;
    int b   = e/(9*HW);
    int r   = e % (9*HW);
    int k   = r / HW;
    int pix = r % HW;
    int h = pix >> 7, w = pix & 127;

    const float* omb = g_om + (long)b*27*HW;
    float offx = omb[k*HW + pix];
    float offy = omb[(9+k)*HW + pix];
    float m    = omb[(18+k)*HW + pix];

    float py = (float)(h - 1 + k/3) + offy;
    float px = (float)(w - 1 + k%3) + offx;
    float y0f = floorf(py), x0f = floorf(px);
    float wy = py - y0f, wx = px - x0f;
    int y0 = (int)fmaxf(fminf(y0f, 1e6f), -1e6f);
    int x0 = (int)fmaxf(fminf(x0f, 1e6f), -1e6f);
    int y1 = y0 + 1, x1 = x0 + 1;
    float vy0 = (y0 >= 0 && y0 < Hc) ? 1.f : 0.f;
    float vy1 = (y1 >= 0 && y1 < Hc) ? 1.f : 0.f;
    float vx0 = (x0 >= 0 && x0 < Wc) ? 1.f : 0.f;
    float vx1 = (x1 >= 0 && x1 < Wc) ? 1.f : 0.f;
    float4 wv;
    wv.x = (1.f-wy)*(1.f-wx)*m*vy0*vx0;
    wv.y = (1.f-wy)*wx      *m*vy0*vx1;
    wv.z = wy      *(1.f-wx)*m*vy1*vx0;
    wv.w = wy      *wx      *m*vy1*vx1;
    int y0c = min(max(y0,0),Hc-1), y1c = min(max(y1,0),Hc-1);
    int x0c = min(max(x0,0),Wc-1), x1c = min(max(x1,0),Wc-1);

    int plane = b*9 + k;
    g_pk [plane*HW + pix] = (unsigned)y0c | ((unsigned)y1c<<8) | ((unsigned)x0c<<16) | ((unsigned)x1c<<24);
    g_wt4[plane*HW + pix] = wv;
}

// ---------------- kernel 3: fused deformable sampling + [64 x 576] GEMM, K chunked by 96
// thread layout phase 2: o2 = tid>>3 (o pair), pq = tid&7 (4-pixel group)
__global__ void __launch_bounds__(256,4) k_dcn(const float* __restrict__ x,
                                               const float* __restrict__ dcn_b) {
    __shared__ float    s[96*32];        // s_t[j'][pix] for current chunk (row = 128B)
    __shared__ float    wch[96*64];      // weight chunk [j'][o]
    __shared__ unsigned pk_s[288];       // [pix][k]
    __shared__ float4   wt4_s[288];      // [pix][k]

    int wt = blockIdx.x, h = blockIdx.y, b = blockIdx.z;
    int tid = threadIdx.x;
    int w0 = wt*32;

    // stage per-pixel bilinear setup (coalesced plane reads)
    {
        int base = h*Wc + w0;
        for (int i = tid; i < 288; i += 256) {
            int k = i >> 5, pix = i & 31;
            int g = (b*9 + k)*HW + base + pix;
            pk_s [pix*9 + k] = g_pk[g];
            wt4_s[pix*9 + k] = g_wt4[g];
        }
    }
    __syncthreads();

    int o2 = tid >> 3;                    // 0..31 (pair of output channels)
    int pq = tid & 7;                     // 0..7  (4-pixel group)
    int pair = tid >> 5, pix = tid & 31;  // gather roles
    const float* xb = x + (long)b*Cc*HW;

    unsigned long long acc2[4];
    {
        float b0 = __ldg(&dcn_b[2*o2]);
        float b1 = __ldg(&dcn_b[2*o2+1]);
        acc2[0] = acc2[1] = pack2(b0, b0);
        acc2[2] = acc2[3] = pack2(b1, b1);
    }

    for (int ch = 0; ch < 6; ch++) {
        // ---- stage weight chunk: contiguous 24KB copy from g_wT (conflict-free) ----
        {
            const float4* src = (const float4*)(g_wT + ch*96*64);
            float4* dst = (float4*)wch;
            #pragma unroll
            for (int i = tid; i < 96*64/4; i += 256) dst[i] = src[i];
        }
        // ---- gather 96 j's for 32 pixels ----
        {
            int j0 = ch*96 + pair;
            int c = j0 / 9;
            int k = j0 - c*9;
            const float* xp = xb + c*HW;
            #pragma unroll 4
            for (int m = 0; m < 12; m++) {
                int e = pix*9 + k;
                unsigned u = pk_s[e];
                float4 wv = wt4_s[e];
                int y0 = u & 255, y1 = (u>>8)&255, x0c = (u>>16)&255, x1c = u>>24;
                float v = wv.x * xp[y0*Wc + x0c]
                        + wv.y * xp[y0*Wc + x1c]
                        + wv.z * xp[y1*Wc + x0c]
                        + wv.w * xp[y1*Wc + x1c];
                s[(pair + m*8)*32 + pix] = v;
                // advance j by 8: k -> (k+8) mod 9; c increments unless k was 0
                if (k == 0) { k = 8; } else { k--; xp += HW; }
            }
        }
        __syncthreads();

        // ---- GEMM on chunk: acc[o][pix] += wch[j][o] * s[j][pix] ----
        // warp reads 8 distinct 16B s-chunks per j = one full 128B crossbar line
        {
            const float* sbase = s + pq*4;
            const float* wbase = wch + o2*2;
            #pragma unroll 8
            for (int j = 0; j < 96; j++) {
                ulonglong2 sv = *(const ulonglong2*)(sbase + j*32);
                float2 wv = *(const float2*)(wbase + j*64);
                unsigned long long wd0 = pack2(wv.x, wv.x);
                unsigned long long wd1 = pack2(wv.y, wv.y);
                fma2(acc2[0], sv.x, wd0);
                fma2(acc2[1], sv.y, wd0);
                fma2(acc2[2], sv.x, wd1);
                fma2(acc2[3], sv.y, wd1);
            }
        }
        __syncthreads();
    }
    float* op0 = g_pre + ((long)b*Onc + 2*o2)*HW + h*Wc + w0 + pq*4;
    *(ulonglong2*)(op0)      = make_ulonglong2(acc2[0], acc2[1]);
    *(ulonglong2*)(op0 + HW) = make_ulonglong2(acc2[2], acc2[3]);
}

// ---------------- kernel 4a: partial per-channel sums (1024 blocks, deterministic)
__global__ void k_bnstats1() {
    __shared__ float r1[256], r2[256];
    int sl = blockIdx.x;       // 0..15 slice
    int o  = blockIdx.y;       // channel
    int tid = threadIdx.x;
    int b = sl >> 2, q = sl & 3;
    const float4* p = (const float4*)(g_pre + ((long)(b*Onc + o))*HW + q*4096);
    float sm = 0.f, sq = 0.f;
    #pragma unroll
    for (int i = tid; i < 1024; i += 256) {
        float4 v = p[i];
        sm += v.x + v.y + v.z + v.w;
        sq += v.x*v.x + v.y*v.y + v.z*v.z + v.w*v.w;
    }
    r1[tid] = sm; r2[tid] = sq; __syncthreads();
    for (int st = 128; st > 0; st >>= 1) {
        if (tid < st) { r1[tid] += r1[tid+st]; r2[tid] += r2[tid+st]; }
        __syncthreads();
    }
    if (tid == 0) { g_psum[o*16 + sl] = r1[0]; g_psq[o*16 + sl] = r2[0]; }
}

// ---------------- kernel 4b: finalize scale/shift
__global__ void k_bnstats2(const float* __restrict__ gamma, const float* __restrict__ beta) {
    int o = threadIdx.x;
    float sm = 0.f, sq = 0.f;
    #pragma unroll
    for (int i = 0; i < 16; i++) { sm += g_psum[o*16+i]; sq += g_psq[o*16+i]; }
    float n   = (float)(Bc*HW);
    float mu  = sm/n;
    float var = sq/n - mu*mu;
    float sc  = __ldg(&gamma[o]) * rsqrtf(var + 1e-5f);
    g_scale[o] = sc;
    g_shift[o] = __ldg(&beta[o]) - mu*sc;
}

// ---------------- kernel 5: BN apply + ReLU
__global__ void k_bnapply(float* __restrict__ out) {
    int i = blockIdx.x*256 + threadIdx.x;  // float4 index
    int e = i*4;
    int o = (e >> 14) & 63;                // plane = 16384 elems
    float4 v = *(const float4*)(g_pre + e);
    float sc = g_scale[o], sf = g_shift[o];
    float4 r;
    r.x = fmaxf(fmaf(v.x, sc, sf), 0.f);
    r.y = fmaxf(fmaf(v.y, sc, sf), 0.f);
    r.z = fmaxf(fmaf(v.z, sc, sf), 0.f);
    r.w = fmaxf(fmaf(v.w, sc, sf), 0.f);
    *(float4*)(out + e) = r;
}

extern "C" void kernel_launch(void* const* d_in, const int* in_sizes, int n_in,
                              void* d_out, int out_size) {
    const float* x  = (const float*)d_in[0];
    const float* ow = (const float*)d_in[1];
    const float* ob = (const float*)d_in[2];
    const float* dw = (const float*)d_in[3];
    const float* db = (const float*)d_in[4];
    const float* ga = (const float*)d_in[5];
    const float* be = (const float*)d_in[6];
    float* out = (float*)d_out;

    cudaFuncSetAttribute(k_offconv, cudaFuncAttributeMaxDynamicSharedMemorySize, 576*28*4);

    k_transpose<<<144, 256>>>(dw);                          // launch 0

    dim3 g1(Hc/2, Bc);
    k_offconv<<<g1, 128, 576*28*4>>>(x, ow, ob);            // launch 1

    k_prep<<<(Bc*9*HW + 255)/256, 256>>>();                 // launch 2

    dim3 g2(Wc/32, Hc, Bc);
    k_dcn<<<g2, 256>>>(x, db);                              // launch 3 (ncu capture slot)

    dim3 g3(16, Onc);
    k_bnstats1<<<g3, 256>>>();                              // launch 4
    k_bnstats2<<<1, Onc>>>(ga, be);                         // launch 5

    k_bnapply<<<(Bc*Onc*HW)/4/256, 256>>>(out);             // launch 6
}

// round 12
// speedup vs baseline: 1.5721x; 1.1738x over previous
#include <cuda_runtime.h>
#include <math.h>

#define Bc 4
#define Cc 64
#define Onc 64
#define Hc 128
#define Wc 128
#define HW (Hc*Wc)

// -------- scratch (device globals: allocation-free) --------
__device__ float  g_om[Bc*27*HW];       // offset-conv output (mask pre-sigmoided)
__device__ float  g_wT[576*Onc];        // dcn weights transposed [j][o]
__device__ float  g_pre[Bc*Onc*HW];     // pre-BN output
__device__ unsigned g_pk [Bc*9*HW];     // packed clamped corner coords, planes [b][k][pix]
__device__ float4 g_wt4[Bc*9*HW];       // bilinear weights (validity+mask folded), [b][k][pix]
__device__ float  g_scale[Onc];
__device__ float  g_shift[Onc];
__device__ float  g_psum[Onc*16];
__device__ float  g_psq[Onc*16];

// ---- packed fp32x2 helpers (Blackwell FFMA2, PTX-only) ----
__device__ __forceinline__ unsigned long long pack2(float lo, float hi) {
    unsigned long long r;
    asm("mov.b64 %0, {%1,%2};" : "=l"(r) : "f"(lo), "f"(hi));
    return r;
}
__device__ __forceinline__ void fma2(unsigned long long& d,
                                     unsigned long long a, unsigned long long b) {
    asm("fma.rn.f32x2 %0, %1, %2, %0;" : "+l"(d) : "l"(a), "l"(b));
}
__device__ __forceinline__ float2 unpack2(unsigned long long v) {
    float2 f;
    asm("mov.b64 {%0,%1}, %2;" : "=f"(f.x), "=f"(f.y) : "l"(v));
    return f;
}

// ---------------- kernel 0: transpose dcn weights [O][576] -> [576][O]
__global__ void k_transpose(const float* __restrict__ w) {
    int i = blockIdx.x*256 + threadIdx.x;
    if (i < Onc*576) {
        int o = i / 576, j = i - o*576;
        g_wT[j*Onc + o] = w[i];
    }
}

// ---------------- kernel 1: offset conv (27ch, 3x3, pad 1) + sigmoid on mask chans
__global__ void __launch_bounds__(128) k_offconv(const float* __restrict__ x,
                                                 const float* __restrict__ ow,
                                                 const float* __restrict__ ob) {
    extern __shared__ float wsh[]; // [c*9+k][28]
    int b = blockIdx.y;
    int tid = threadIdx.x;                // = w (0..127)
    for (int i = tid; i < 27*576; i += 128) {
        int oc = i / 576, r = i - oc*576;
        wsh[r*28 + oc] = ow[i];
    }
    __syncthreads();

    int w = tid;
    const float* xb = x + (long)b*Cc*HW;

    for (int hh = 0; hh < 2; hh++) {
        int h = blockIdx.x*2 + hh;

        unsigned long long acc2[14];
        #pragma unroll
        for (int q = 0; q < 14; q++) {
            float b0 = (2*q   < 27) ? __ldg(&ob[2*q])   : 0.f;
            float b1 = (2*q+1 < 27) ? __ldg(&ob[2*q+1]) : 0.f;
            acc2[q] = pack2(b0, b1);
        }

        for (int c = 0; c < Cc; c++) {
            const float* p = xb + c*HW;
            float v[9];
            #pragma unroll
            for (int dy = 0; dy < 3; dy++) {
                int yy = h - 1 + dy;
                bool yok = (unsigned)yy < (unsigned)Hc;
                const float* row = p + yy*Wc;
                v[dy*3+0] = (yok && w >= 1)    ? row[w-1] : 0.f;
                v[dy*3+1] =  yok               ? row[w]   : 0.f;
                v[dy*3+2] = (yok && w <= Wc-2) ? row[w+1] : 0.f;
            }
            #pragma unroll
            for (int k = 0; k < 9; k++) {
                unsigned long long vk2 = pack2(v[k], v[k]);
                const ulonglong2* wr = (const ulonglong2*)&wsh[(c*9+k)*28];
                #pragma unroll
                for (int q = 0; q < 7; q++) {
                    ulonglong2 wv = wr[q];
                    fma2(acc2[q*2+0], vk2, wv.x);
                    fma2(acc2[q*2+1], vk2, wv.y);
                }
            }
        }
        float accf[28];
        #pragma unroll
        for (int q = 0; q < 14; q++) {
            float2 u = unpack2(acc2[q]);
            accf[2*q] = u.x; accf[2*q+1] = u.y;
        }
        float* outp = g_om + ((long)b*27*HW) + h*Wc + w;
        #pragma unroll
        for (int oc = 0; oc < 27; oc++) {
            float vv = accf[oc];
            if (oc >= 18) vv = 1.f/(1.f + expf(-vv));   // sigmoid mask channels
            outp[oc*HW] = vv;
        }
    }
}

// ---------------- kernel 2: per-(pixel,tap) bilinear setup, fully coalesced (all batches)
__global__ void __launch_bounds__(256) k_prep() {
    int e = blockIdx.x*256 + threadIdx.x;      // over 4*9*HW
    if (e >= Bc*9*HW) return;
    int b   = e/(9*HW);
    int r   = e % (9*HW);
    int k   = r / HW;
    int pix = r % HW;
    int h = pix >> 7, w = pix & 127;

    const float* omb = g_om + (long)b*27*HW;
    float offx = omb[k*HW + pix];
    float offy = omb[(9+k)*HW + pix];
    float m    = omb[(18+k)*HW + pix];

    float py = (float)(h - 1 + k/3) + offy;
    float px = (float)(w - 1 + k%3) + offx;
    float y0f = floorf(py), x0f = floorf(px);
    float wy = py - y0f, wx = px - x0f;
    int y0 = (int)fmaxf(fminf(y0f, 1e6f), -1e6f);
    int x0 = (int)fmaxf(fminf(x0f, 1e6f), -1e6f);
    int y1 = y0 + 1, x1 = x0 + 1;
    float vy0 = (y0 >= 0 && y0 < Hc) ? 1.f : 0.f;
    float vy1 = (y1 >= 0 && y1 < Hc) ? 1.f : 0.f;
    float vx0 = (x0 >= 0 && x0 < Wc) ? 1.f : 0.f;
    float vx1 = (x1 >= 0 && x1 < Wc) ? 1.f : 0.f;
    float4 wv;
    wv.x = (1.f-wy)*(1.f-wx)*m*vy0*vx0;
    wv.y = (1.f-wy)*wx      *m*vy0*vx1;
    wv.z = wy      *(1.f-wx)*m*vy1*vx0;
    wv.w = wy      *wx      *m*vy1*vx1;
    int y0c = min(max(y0,0),Hc-1), y1c = min(max(y1,0),Hc-1);
    int x0c = min(max(x0,0),Wc-1), x1c = min(max(x1,0),Wc-1);

    int plane = b*9 + k;
    g_pk [plane*HW + pix] = (unsigned)y0c | ((unsigned)y1c<<8) | ((unsigned)x0c<<16) | ((unsigned)x1c<<24);
    g_wt4[plane*HW + pix] = wv;
}

// ---------------- kernel 3: fused sampling + GEMM. 128-pixel row tile, To=4 x Tp=8.
// smem (dynamic, 59904B): wt4_s[9][128] f4 | s[48][128] | wch[48][64] | pk_s[9][128]
__global__ void __launch_bounds__(256) k_dcn(const float* __restrict__ x,
                                             const float* __restrict__ dcn_b) {
    extern __shared__ float sh[];
    float4*   wt4_s = (float4*)sh;                 // 9*128 float4 = 18432B
    float*    s     = sh + 4*9*128;                // 48*128 = 24576B
    float*    wch   = s + 48*128;                  // 48*64  = 12288B
    unsigned* pk_s  = (unsigned*)(wch + 48*64);    // 9*128  = 4608B

    int h = blockIdx.x, b = blockIdx.y;
    int tid = threadIdx.x;

    // stage per-pixel bilinear setup as [k][pix] planes (coalesced both ways)
    {
        int base = h*Wc;
        for (int i = tid; i < 9*128; i += 256) {
            int k = i >> 7, pix = i & 127;
            int g = (b*9 + k)*HW + base + pix;
            pk_s [i] = g_pk[g];
            wt4_s[i] = g_wt4[g];
        }
    }
    __syncthreads();

    int pix = tid & 127, jset = tid >> 7;   // gather roles: 2 j-sets x 128 pixels
    int oi  = tid & 15,  pi   = tid >> 4;   // GEMM roles: o = oi*4.., pix = pi*8..
    const float* xb = x + (long)b*Cc*HW;

    unsigned long long acc2[4][4];          // [oq][pixpair]
    #pragma unroll
    for (int oq = 0; oq < 4; oq++) {
        float bo = __ldg(&dcn_b[oi*4 + oq]);
        unsigned long long bb = pack2(bo, bo);
        #pragma unroll
        for (int pp = 0; pp < 4; pp++) acc2[oq][pp] = bb;
    }

    for (int ch = 0; ch < 12; ch++) {
        // ---- stage weight chunk: contiguous 12KB copy (conflict-free) ----
        {
            const float4* src = (const float4*)(g_wT + ch*48*64);
            float4* dst = (float4*)wch;
            #pragma unroll
            for (int i = tid; i < 48*64/4; i += 256) dst[i] = src[i];
        }
        // ---- gather 48 j's for 128 pixels (24 samples/thread) ----
        {
            int j0 = ch*48 + jset;
            int c = j0 / 9;
            int k = j0 - c*9;
            const float* xp = xb + c*HW;
            #pragma unroll 4
            for (int m = 0; m < 24; m++) {
                unsigned u = pk_s[k*128 + pix];
                float4 wv = wt4_s[k*128 + pix];
                int y0 = u & 255, y1 = (u>>8)&255, x0c = (u>>16)&255, x1c = u>>24;
                float v = wv.x * xp[y0*Wc + x0c]
                        + wv.y * xp[y0*Wc + x1c]
                        + wv.z * xp[y1*Wc + x0c]
                        + wv.w * xp[y1*Wc + x1c];
                s[(jset + 2*m)*128 + pix] = v;
                k += 2;
                if (k >= 9) { k -= 9; c++; xp += HW; }
            }
        }
        __syncthreads();

        // ---- GEMM on chunk: acc[4 o][8 pix] += wch[j][o] * s[j][pix] ----
        {
            const float* sbase = s + pi*8;
            const float* wbase = wch + oi*4;
            #pragma unroll 6
            for (int j = 0; j < 48; j++) {
                float4 w4 = *(const float4*)(wbase + j*64);
                ulonglong2 sA = *(const ulonglong2*)(sbase + j*128);      // pix 0-3
                ulonglong2 sB = *(const ulonglong2*)(sbase + j*128 + 4);  // pix 4-7
                float wq[4] = {w4.x, w4.y, w4.z, w4.w};
                #pragma unroll
                for (int oq = 0; oq < 4; oq++) {
                    unsigned long long wd = pack2(wq[oq], wq[oq]);
                    fma2(acc2[oq][0], sA.x, wd);
                    fma2(acc2[oq][1], sA.y, wd);
                    fma2(acc2[oq][2], sB.x, wd);
                    fma2(acc2[oq][3], sB.y, wd);
                }
            }
        }
        __syncthreads();
    }
    #pragma unroll
    for (int oq = 0; oq < 4; oq++) {
        float* op = g_pre + ((long)b*Onc + oi*4 + oq)*HW + h*Wc + pi*8;
        *(ulonglong2*)(op)     = make_ulonglong2(acc2[oq][0], acc2[oq][1]);
        *(ulonglong2*)(op + 4) = make_ulonglong2(acc2[oq][2], acc2[oq][3]);
    }
}

// ---------------- kernel 4a: partial per-channel sums (1024 blocks, deterministic)
__global__ void k_bnstats1() {
    __shared__ float r1[256], r2[256];
    int sl = blockIdx.x;       // 0..15 slice
    int o  = blockIdx.y;       // channel
    int tid = threadIdx.x;
    int b = sl >> 2, q = sl & 3;
    const float4* p = (const float4*)(g_pre + ((long)(b*Onc + o))*HW + q*4096);
    float sm = 0.f, sq = 0.f;
    #pragma unroll
    for (int i = tid; i < 1024; i += 256) {
        float4 v = p[i];
        sm += v.x + v.y + v.z + v.w;
        sq += v.x*v.x + v.y*v.y + v.z*v.z + v.w*v.w;
    }
    r1[tid] = sm; r2[tid] = sq; __syncthreads();
    for (int st = 128; st > 0; st >>= 1) {
        if (tid < st) { r1[tid] += r1[tid+st]; r2[tid] += r2[tid+st]; }
        __syncthreads();
    }
    if (tid == 0) { g_psum[o*16 + sl] = r1[0]; g_psq[o*16 + sl] = r2[0]; }
}

// ---------------- kernel 4b: finalize scale/shift
__global__ void k_bnstats2(const float* __restrict__ gamma, const float* __restrict__ beta) {
    int o = threadIdx.x;
    float sm = 0.f, sq = 0.f;
    #pragma unroll
    for (int i = 0; i < 16; i++) { sm += g_psum[o*16+i]; sq += g_psq[o*16+i]; }
    float n   = (float)(Bc*HW);
    float mu  = sm/n;
    float var = sq/n - mu*mu;
    float sc  = __ldg(&gamma[o]) * rsqrtf(var + 1e-5f);
    g_scale[o] = sc;
    g_shift[o] = __ldg(&beta[o]) - mu*sc;
}

// ---------------- kernel 5: BN apply + ReLU
__global__ void k_bnapply(float* __restrict__ out) {
    int i = blockIdx.x*256 + threadIdx.x;  // float4 index
    int e = i*4;
    int o = (e >> 14) & 63;                // plane = 16384 elems
    float4 v = *(const float4*)(g_pre + e);
    float sc = g_scale[o], sf = g_shift[o];
    float4 r;
    r.x = fmaxf(fmaf(v.x, sc, sf), 0.f);
    r.y = fmaxf(fmaf(v.y, sc, sf), 0.f);
    r.z = fmaxf(fmaf(v.z, sc, sf), 0.f);
    r.w = fmaxf(fmaf(v.w, sc, sf), 0.f);
    *(float4*)(out + e) = r;
}

extern "C" void kernel_launch(void* const* d_in, const int* in_sizes, int n_in,
                              void* d_out, int out_size) {
    const float* x  = (const float*)d_in[0];
    const float* ow = (const float*)d_in[1];
    const float* ob = (const float*)d_in[2];
    const float* dw = (const float*)d_in[3];
    const float* db = (const float*)d_in[4];
    const float* ga = (const float*)d_in[5];
    const float* be = (const float*)d_in[6];
    float* out = (float*)d_out;

    cudaFuncSetAttribute(k_offconv, cudaFuncAttributeMaxDynamicSharedMemorySize, 576*28*4);
    cudaFuncSetAttribute(k_dcn,     cudaFuncAttributeMaxDynamicSharedMemorySize, 59904);

    k_transpose<<<144, 256>>>(dw);                          // launch 0

    dim3 g1(Hc/2, Bc);
    k_offconv<<<g1, 128, 576*28*4>>>(x, ow, ob);            // launch 1

    k_prep<<<(Bc*9*HW + 255)/256, 256>>>();                 // launch 2

    dim3 g2(Hc, Bc);
    k_dcn<<<g2, 256, 59904>>>(x, db);                       // launch 3 (ncu capture slot)

    dim3 g3(16, Onc);
    k_bnstats1<<<g3, 256>>>();                              // launch 4
    k_bnstats2<<<1, Onc>>>(ga, be);                         // launch 5

    k_bnapply<<<(Bc*Onc*HW)/4/256, 256>>>(out);             // launch 6
}